// round 10
// baseline (speedup 1.0000x reference)
#include <cuda_runtime.h>
#include <cuda_bf16.h>
#include <cstdint>
#include <math.h>

#define Bb 32
#define Nn 2048
#define Mm 512
#define Dd 512

#define BM 128
#define BN 64
#define BK 32
#define PK 40   // smem pitch in bf16 elements (conflict-free for ldmatrix)

// Stage layouts in elements (u16), per pipeline stage:
//  2-operand gemms: Ah 0, Al 5120, Bh 10240, Bl 12800; stage = 15360 (30720B)
//  3-operand gemm : Ah 0, Al 5120, B1h 10240, B1l 12800, B2h 15360, B2l 17920; stage = 20480 (40960B)
#define STG2 15360
#define STG3 20480

// ---------------------------------------------------------------------------
// Scratch (static device globals — allocation-free), round-5 set verbatim
// ---------------------------------------------------------------------------
__device__ float g_E [(size_t)Bb*Nn*Mm];   // exp(S)   [b][n][m]
__device__ float g_Et[(size_t)Bb*Nn*Mm];   // E^T      [b][m][n]
__device__ float g_Ct[(size_t)Bb*Nn*Dd];   // C^T      [b][d][n]
__device__ float g_Qt[(size_t)Bb*Mm*Dd];   // Q^T      [b][d][m]
__device__ float g_Tt[(size_t)Bb*Mm*Dd];   // T^T      [b][d][m]
__device__ float g_rowC[Bb*Nn];
__device__ float g_rowQ[Bb*Mm];
__device__ float g_rcpRow[Bb*Nn];
__device__ float g_rcpCol[Bb*Mm];

// ---------------------------------------------------------------------------
// MMA helpers (baseline PTX — no 'a' features)
// ---------------------------------------------------------------------------
__device__ __forceinline__ uint32_t smem_u32(const void* p){
    uint32_t a;
    asm("{ .reg .u64 t; cvta.to.shared.u64 t, %1; cvt.u32.u64 %0, t; }"
        : "=r"(a) : "l"(p));
    return a;
}

__device__ __forceinline__ void ldm_x4(uint32_t* r, const uint16_t* p){
    uint32_t a = smem_u32(p);
    asm volatile("ldmatrix.sync.aligned.m8n8.x4.shared.b16 {%0,%1,%2,%3}, [%4];"
        : "=r"(r[0]), "=r"(r[1]), "=r"(r[2]), "=r"(r[3]) : "r"(a));
}

__device__ __forceinline__ void mma_bf16(float* c, const uint32_t* a,
                                         uint32_t b0, uint32_t b1){
    asm volatile("mma.sync.aligned.m16n8k16.row.col.f32.bf16.bf16.f32 "
        "{%0,%1,%2,%3}, {%4,%5,%6,%7}, {%8,%9}, {%0,%1,%2,%3};"
        : "+f"(c[0]), "+f"(c[1]), "+f"(c[2]), "+f"(c[3])
        : "r"(a[0]), "r"(a[1]), "r"(a[2]), "r"(a[3]), "r"(b0), "r"(b1));
}

// ---------------------------------------------------------------------------
// Register fragments for double-buffered global loads (round-5 verbatim)
// ---------------------------------------------------------------------------
template<int ROWS>
struct TileFrag { float4 v[ROWS/32]; };

template<int ROWS>
__device__ __forceinline__ void frag_load(TileFrag<ROWS>& f,
    const float* __restrict__ src, int pitch, int r0, int k0, int tid)
{
    int rr = tid >> 3;            // 0..31
    int c4 = (tid & 7) * 4;       // 0,4,...,28
#pragma unroll
    for (int it = 0; it < ROWS/32; it++)
        f.v[it] = *reinterpret_cast<const float4*>(
            src + (size_t)(r0 + rr + it*32)*pitch + k0 + c4);
}

template<int ROWS>
__device__ __forceinline__ void frag_stage(const TileFrag<ROWS>& f,
    uint16_t* __restrict__ hi, uint16_t* __restrict__ lo,
    const float* __restrict__ wvec, const int* __restrict__ kmask,
    int k0, int tid)
{
    int rr = tid >> 3;
    int c4 = (tid & 7) * 4;
    float4 wv = make_float4(1.f, 1.f, 1.f, 1.f);
    if (wvec) wv = *reinterpret_cast<const float4*>(wvec + k0 + c4);
    int4 mk = make_int4(0, 0, 0, 0);
    if (kmask) mk = *reinterpret_cast<const int4*>(kmask + k0 + c4);
#pragma unroll
    for (int it = 0; it < ROWS/32; it++){
        int r = rr + it*32;
        float4 v = f.v[it];
        v.x *= wv.x; v.y *= wv.y; v.z *= wv.z; v.w *= wv.w;
        if (kmask){
            v.x = mk.x ? 0.f : v.x;  v.y = mk.y ? 0.f : v.y;
            v.z = mk.z ? 0.f : v.z;  v.w = mk.w ? 0.f : v.w;
        }
        __nv_bfloat16 hx = __float2bfloat16_rn(v.x);
        __nv_bfloat16 hy = __float2bfloat16_rn(v.y);
        __nv_bfloat16 hz = __float2bfloat16_rn(v.z);
        __nv_bfloat16 hw = __float2bfloat16_rn(v.w);
        __nv_bfloat16 lx = __float2bfloat16_rn(v.x - __bfloat162float(hx));
        __nv_bfloat16 ly = __float2bfloat16_rn(v.y - __bfloat162float(hy));
        __nv_bfloat16 lz = __float2bfloat16_rn(v.z - __bfloat162float(hz));
        __nv_bfloat16 lw = __float2bfloat16_rn(v.w - __bfloat162float(hw));
        uint32_t off = r*PK + c4;
        *reinterpret_cast<__nv_bfloat162*>(hi + off)     = __halves2bfloat162(hx, hy);
        *reinterpret_cast<__nv_bfloat162*>(hi + off + 2) = __halves2bfloat162(hz, hw);
        *reinterpret_cast<__nv_bfloat162*>(lo + off)     = __halves2bfloat162(lx, ly);
        *reinterpret_cast<__nv_bfloat162*>(lo + off + 2) = __halves2bfloat162(lz, lw);
    }
}

// ---------------------------------------------------------------------------
// Warp MMA on one staged BK=32 chunk; warp tile 32x32; bf16x3 (hh+hl+lh)
// ---------------------------------------------------------------------------
__device__ __forceinline__ void warp_mma_tile(
    float acc[2][4][4],
    const uint16_t* __restrict__ Ahi, const uint16_t* __restrict__ Alo,
    const uint16_t* __restrict__ Bhi, const uint16_t* __restrict__ Blo,
    int wm, int wn, int lane)
{
    int rsel = lane & 15;
    int ksel = (lane >> 4) * 8;
#pragma unroll
    for (int ks = 0; ks < 2; ks++){
        uint32_t ah[2][4], al[2][4];
#pragma unroll
        for (int mt = 0; mt < 2; mt++){
            ldm_x4(ah[mt], Ahi + (wm*32 + mt*16 + rsel)*PK + ks*16 + ksel);
            ldm_x4(al[mt], Alo + (wm*32 + mt*16 + rsel)*PK + ks*16 + ksel);
        }
        uint32_t bh[2][4], bl[2][4];
#pragma unroll
        for (int g = 0; g < 2; g++){
            ldm_x4(bh[g], Bhi + (wn*32 + g*16 + rsel)*PK + ks*16 + ksel);
            ldm_x4(bl[g], Blo + (wn*32 + g*16 + rsel)*PK + ks*16 + ksel);
        }
#pragma unroll
        for (int mt = 0; mt < 2; mt++)
#pragma unroll
        for (int nt = 0; nt < 4; nt++){
            uint32_t b0h = bh[nt>>1][nt & 1], b1h = bh[nt>>1][(nt & 1) + 2];
            uint32_t b0l = bl[nt>>1][nt & 1], b1l = bl[nt>>1][(nt & 1) + 2];
            mma_bf16(acc[mt][nt], ah[mt], b0h, b1h);
            mma_bf16(acc[mt][nt], ah[mt], b0l, b1l);
            mma_bf16(acc[mt][nt], al[mt], b0h, b1h);
        }
    }
}

// ---------------------------------------------------------------------------
// gemmS: E[b,n,m] = exp( rowC[n] + rowQ[m] + sum_d (C*w3)[n,d]*Q[m,d] )
// Double-buffered smem staging, one sync per chunk.
// ---------------------------------------------------------------------------
__global__ void __launch_bounds__(256) gemmS_mma(
    const float* __restrict__ C, const float* __restrict__ Q,
    const float* __restrict__ w)
{
    extern __shared__ uint16_t sm[];
    int tid = threadIdx.x, lane = tid & 31, wid = tid >> 5;
    int wm = wid >> 1, wn = wid & 1;
    int b = blockIdx.z, n0 = blockIdx.y*BM, m0 = blockIdx.x*BN;
    const float* Cb = C + (size_t)b*Nn*Dd;
    const float* Qb = Q + (size_t)b*Mm*Dd;
    const float* w3 = w + 2*Dd;
    const int NCH = Dd/BK;

    TileFrag<BM> fa; TileFrag<BN> fb;
    frag_load(fa, Cb, Dd, n0, 0, tid);
    frag_load(fb, Qb, Dd, m0, 0, tid);
    frag_stage(fa, sm,          sm + 5120,  w3, nullptr, 0, tid);
    frag_stage(fb, sm + 10240,  sm + 12800, nullptr, nullptr, 0, tid);
    frag_load(fa, Cb, Dd, n0, BK, tid);
    frag_load(fb, Qb, Dd, m0, BK, tid);
    __syncthreads();

    float acc[2][4][4] = {};
    for (int k = 0; k < NCH; k++){
        if (k + 1 < NCH){
            uint16_t* s = sm + ((k+1)&1)*STG2;
            frag_stage(fa, s,         s + 5120,  w3, nullptr, (k+1)*BK, tid);
            frag_stage(fb, s + 10240, s + 12800, nullptr, nullptr, (k+1)*BK, tid);
            if (k + 2 < NCH){
                frag_load(fa, Cb, Dd, n0, (k+2)*BK, tid);
                frag_load(fb, Qb, Dd, m0, (k+2)*BK, tid);
            }
        }
        const uint16_t* c = sm + (k&1)*STG2;
        warp_mma_tile(acc, c, c + 5120, c + 10240, c + 12800, wm, wn, lane);
        __syncthreads();
    }

    int rg = lane >> 2, cg = (lane & 3)*2;
#pragma unroll
    for (int mt = 0; mt < 2; mt++)
#pragma unroll
    for (int nt = 0; nt < 4; nt++)
#pragma unroll
    for (int h = 0; h < 2; h++){
        int n = n0 + wm*32 + mt*16 + rg + h*8;
        int m = m0 + wn*32 + nt*8 + cg;
        float rc = g_rowC[b*Nn + n];
        float2 o;
        o.x = __expf(acc[mt][nt][h*2+0] + rc + g_rowQ[b*Mm + m + 0]);
        o.y = __expf(acc[mt][nt][h*2+1] + rc + g_rowQ[b*Mm + m + 1]);
        *reinterpret_cast<float2*>(&g_E[(size_t)(b*Nn + n)*Mm + m]) = o;
    }
}

// ---------------------------------------------------------------------------
// gemmT: Tt[b,d,m] = rcpCol[m] * sum_n Ct[d,n] * (Cmask[n]? 0 : Et[m,n])
// ---------------------------------------------------------------------------
__global__ void __launch_bounds__(256) gemmT_mma(const int* __restrict__ Cmask)
{
    extern __shared__ uint16_t sm[];
    int tid = threadIdx.x, lane = tid & 31, wid = tid >> 5;
    int wm = wid >> 1, wn = wid & 1;
    int b = blockIdx.z, d0 = blockIdx.y*BM, m0 = blockIdx.x*BN;
    const float* Ab = g_Ct + (size_t)b*Dd*Nn;   // [d][n]
    const float* Bp = g_Et + (size_t)b*Mm*Nn;   // [m][n]
    const int*   cm = Cmask + b*Nn;
    const int NCH = Nn/BK;

    TileFrag<BM> fa; TileFrag<BN> fb;
    frag_load(fa, Ab, Nn, d0, 0, tid);
    frag_load(fb, Bp, Nn, m0, 0, tid);
    frag_stage(fa, sm,         sm + 5120,  nullptr, nullptr, 0, tid);
    frag_stage(fb, sm + 10240, sm + 12800, nullptr, cm, 0, tid);
    frag_load(fa, Ab, Nn, d0, BK, tid);
    frag_load(fb, Bp, Nn, m0, BK, tid);
    __syncthreads();

    float acc[2][4][4] = {};
    for (int k = 0; k < NCH; k++){
        if (k + 1 < NCH){
            uint16_t* s = sm + ((k+1)&1)*STG2;
            frag_stage(fa, s,         s + 5120,  nullptr, nullptr, (k+1)*BK, tid);
            frag_stage(fb, s + 10240, s + 12800, nullptr, cm, (k+1)*BK, tid);
            if (k + 2 < NCH){
                frag_load(fa, Ab, Nn, d0, (k+2)*BK, tid);
                frag_load(fb, Bp, Nn, m0, (k+2)*BK, tid);
            }
        }
        const uint16_t* c = sm + (k&1)*STG2;
        warp_mma_tile(acc, c, c + 5120, c + 10240, c + 12800, wm, wn, lane);
        __syncthreads();
    }

    int rg = lane >> 2, cg = (lane & 3)*2;
#pragma unroll
    for (int mt = 0; mt < 2; mt++)
#pragma unroll
    for (int nt = 0; nt < 4; nt++)
#pragma unroll
    for (int h = 0; h < 2; h++){
        int d = d0 + wm*32 + mt*16 + rg + h*8;
        int m = m0 + wn*32 + nt*8 + cg;
        float2 o;
        o.x = acc[mt][nt][h*2+0] * g_rcpCol[b*Mm + m + 0];
        o.y = acc[mt][nt][h*2+1] * g_rcpCol[b*Mm + m + 1];
        *reinterpret_cast<float2*>(&g_Tt[((size_t)b*Dd + d)*Mm + m]) = o;
    }
}

// ---------------------------------------------------------------------------
// gemmAB: A   [b,n,d] = rcpRow[n] * sum_m E[n,m] * (Qmask[m]? 0 : Qt[d,m])
//         Bout[b,n,d] = rcpRow[n] * sum_m E[n,m] * (Qmask[m]? 0 : Tt[d,m])
// ---------------------------------------------------------------------------
__global__ void __launch_bounds__(256) gemmAB_mma(
    const int* __restrict__ Qmask, float* __restrict__ outA,
    float* __restrict__ outB)
{
    extern __shared__ uint16_t sm[];
    int tid = threadIdx.x, lane = tid & 31, wid = tid >> 5;
    int wm = wid >> 1, wn = wid & 1;
    int b = blockIdx.z, n0 = blockIdx.y*BM, d0 = blockIdx.x*BN;
    const float* Eb  = g_E  + (size_t)b*Nn*Mm;   // [n][m]
    const float* Qtb = g_Qt + (size_t)b*Dd*Mm;   // [d][m]
    const float* Ttb = g_Tt + (size_t)b*Dd*Mm;   // [d][m]
    const int*   qm  = Qmask + b*Mm;
    const int NCH = Mm/BK;

    TileFrag<BM> fa; TileFrag<BN> fb1, fb2;
    frag_load(fa,  Eb,  Mm, n0, 0, tid);
    frag_load(fb1, Qtb, Mm, d0, 0, tid);
    frag_load(fb2, Ttb, Mm, d0, 0, tid);
    frag_stage(fa,  sm,         sm + 5120,  nullptr, nullptr, 0, tid);
    frag_stage(fb1, sm + 10240, sm + 12800, nullptr, qm, 0, tid);
    frag_stage(fb2, sm + 15360, sm + 17920, nullptr, qm, 0, tid);
    frag_load(fa,  Eb,  Mm, n0, BK, tid);
    frag_load(fb1, Qtb, Mm, d0, BK, tid);
    frag_load(fb2, Ttb, Mm, d0, BK, tid);
    __syncthreads();

    float accA[2][4][4] = {};
    float accB[2][4][4] = {};
    for (int k = 0; k < NCH; k++){
        if (k + 1 < NCH){
            uint16_t* s = sm + ((k+1)&1)*STG3;
            frag_stage(fa,  s,         s + 5120,  nullptr, nullptr, (k+1)*BK, tid);
            frag_stage(fb1, s + 10240, s + 12800, nullptr, qm, (k+1)*BK, tid);
            frag_stage(fb2, s + 15360, s + 17920, nullptr, qm, (k+1)*BK, tid);
            if (k + 2 < NCH){
                frag_load(fa,  Eb,  Mm, n0, (k+2)*BK, tid);
                frag_load(fb1, Qtb, Mm, d0, (k+2)*BK, tid);
                frag_load(fb2, Ttb, Mm, d0, (k+2)*BK, tid);
            }
        }
        const uint16_t* c = sm + (k&1)*STG3;
        warp_mma_tile(accA, c, c + 5120, c + 10240, c + 12800, wm, wn, lane);
        warp_mma_tile(accB, c, c + 5120, c + 15360, c + 17920, wm, wn, lane);
        __syncthreads();
    }

    int rg = lane >> 2, cg = (lane & 3)*2;
#pragma unroll
    for (int mt = 0; mt < 2; mt++)
#pragma unroll
    for (int nt = 0; nt < 4; nt++)
#pragma unroll
    for (int h = 0; h < 2; h++){
        int n = n0 + wm*32 + mt*16 + rg + h*8;
        int d = d0 + wn*32 + nt*8 + cg;
        float rr = g_rcpRow[b*Nn + n];
        size_t idx = (size_t)(b*Nn + n)*Dd + d;
        float2 oa = { accA[mt][nt][h*2+0]*rr, accA[mt][nt][h*2+1]*rr };
        float2 ob = { accB[mt][nt][h*2+0]*rr, accB[mt][nt][h*2+1]*rr };
        *reinterpret_cast<float2*>(&outA[idx]) = oa;
        *reinterpret_cast<float2*>(&outB[idx]) = ob;
    }
}

// ---------------------------------------------------------------------------
// Row-dot kernels (round-5 verbatim)
// ---------------------------------------------------------------------------
__global__ void rowdotC_kernel(const float* __restrict__ C, const float* __restrict__ w)
{
    int warp = (blockIdx.x * blockDim.x + threadIdx.x) >> 5;
    int lane = threadIdx.x & 31;
    if (warp >= Bb * Nn) return;
    const float4* x4 = reinterpret_cast<const float4*>(C + (size_t)warp * Dd);
    const float4* w4 = reinterpret_cast<const float4*>(w);
    float s = 0.f;
#pragma unroll
    for (int j = 0; j < 4; j++){
        float4 a = x4[lane + j*32]; float4 b = w4[lane + j*32];
        s += a.x*b.x + a.y*b.y + a.z*b.z + a.w*b.w;
    }
#pragma unroll
    for (int o = 16; o; o >>= 1) s += __shfl_xor_sync(~0u, s, o);
    if (lane == 0) g_rowC[warp] = s;
}

__global__ void rowdotQ_kernel(const float* __restrict__ Q, const float* __restrict__ w)
{
    int warp = (blockIdx.x * blockDim.x + threadIdx.x) >> 5;
    int lane = threadIdx.x & 31;
    if (warp >= Bb * Mm) return;
    const float4* x4 = reinterpret_cast<const float4*>(Q + (size_t)warp * Dd);
    const float4* w4 = reinterpret_cast<const float4*>(w + Dd);
    float s = 0.f;
#pragma unroll
    for (int j = 0; j < 4; j++){
        float4 a = x4[lane + j*32]; float4 b = w4[lane + j*32];
        s += a.x*b.x + a.y*b.y + a.z*b.z + a.w*b.w;
    }
#pragma unroll
    for (int o = 16; o; o >>= 1) s += __shfl_xor_sync(~0u, s, o);
    if (lane == 0) g_rowQ[warp] = s;
}

// ---------------------------------------------------------------------------
// Transpose kernels (round-5 verbatim)
// ---------------------------------------------------------------------------
__device__ __forceinline__ void transpose_body(
    const float* __restrict__ src, float* __restrict__ dst, int rows, int cols)
{
    __shared__ float t[32][33];
    int b = blockIdx.z;
    const float* s = src + (size_t)b*rows*cols;
    float* d = dst + (size_t)b*rows*cols;
    int c0 = blockIdx.x*32, r0 = blockIdx.y*32;
    int tx = threadIdx.x & 31, ty = threadIdx.x >> 5;
#pragma unroll
    for (int j = 0; j < 4; j++)
        t[ty + 8*j][tx] = s[(size_t)(r0 + ty + 8*j)*cols + c0 + tx];
    __syncthreads();
#pragma unroll
    for (int j = 0; j < 4; j++)
        d[(size_t)(c0 + ty + 8*j)*rows + r0 + tx] = t[tx][ty + 8*j];
}
__global__ void __launch_bounds__(256) transposeC_kernel(const float* __restrict__ C)
{ transpose_body(C, g_Ct, Nn, Dd); }
__global__ void __launch_bounds__(256) transposeQ_kernel(const float* __restrict__ Q)
{ transpose_body(Q, g_Qt, Mm, Dd); }
__global__ void __launch_bounds__(256) transposeE_kernel()
{ transpose_body(g_E, g_Et, Nn, Mm); }

// ---------------------------------------------------------------------------
// Masked reductions -> reciprocals (round-5 verbatim)
// ---------------------------------------------------------------------------
__global__ void rowsum_kernel(const int* __restrict__ Qmask)
{
    int warp = (blockIdx.x * blockDim.x + threadIdx.x) >> 5;
    int lane = threadIdx.x & 31;
    if (warp >= Bb * Nn) return;
    int b = warp / Nn;
    const float4* e4 = reinterpret_cast<const float4*>(g_E + (size_t)warp * Mm);
    const int4*   q4 = reinterpret_cast<const int4*>(Qmask + b * Mm);
    float s = 0.f;
#pragma unroll
    for (int j = 0; j < 4; j++){
        float4 v = e4[lane + j*32];
        int4   q = q4[lane + j*32];
        s += (q.x ? 0.f : v.x) + (q.y ? 0.f : v.y) + (q.z ? 0.f : v.z) + (q.w ? 0.f : v.w);
    }
#pragma unroll
    for (int o = 16; o; o >>= 1) s += __shfl_xor_sync(~0u, s, o);
    if (lane == 0) g_rcpRow[warp] = 1.f / s;
}

__global__ void colsumT_kernel(const int* __restrict__ Cmask)
{
    int warp = (blockIdx.x * blockDim.x + threadIdx.x) >> 5;
    int lane = threadIdx.x & 31;
    if (warp >= Bb * Mm) return;
    int b = warp / Mm;
    const float4* e4 = reinterpret_cast<const float4*>(g_Et + (size_t)warp * Nn);
    const int4*   c4 = reinterpret_cast<const int4*>(Cmask + b * Nn);
    float s = 0.f;
#pragma unroll
    for (int j = 0; j < 16; j++){
        float4 v = e4[lane + j*32];
        int4   c = c4[lane + j*32];
        s += (c.x ? 0.f : v.x) + (c.y ? 0.f : v.y) + (c.z ? 0.f : v.z) + (c.w ? 0.f : v.w);
    }
#pragma unroll
    for (int o = 16; o; o >>= 1) s += __shfl_xor_sync(~0u, s, o);
    if (lane == 0) g_rcpCol[warp] = 1.f / s;
}

// ---------------------------------------------------------------------------
extern "C" void kernel_launch(void* const* d_in, const int* in_sizes, int n_in,
                              void* d_out, int out_size)
{
    const float* C     = (const float*)d_in[0];
    const float* Q     = (const float*)d_in[1];
    const int*   Cmask = (const int*)d_in[2];
    const int*   Qmask = (const int*)d_in[3];
    const float* w     = (const float*)d_in[4];

    float* outA = (float*)d_out;
    float* outB = outA + (size_t)Bb * Nn * Dd;

    const int SMEM2 = 2*STG2*2;   // 61440 B
    const int SMEM3 = 2*STG3*2;   // 81920 B
    cudaFuncSetAttribute(gemmS_mma,  cudaFuncAttributeMaxDynamicSharedMemorySize, SMEM2);
    cudaFuncSetAttribute(gemmT_mma,  cudaFuncAttributeMaxDynamicSharedMemorySize, SMEM2);
    cudaFuncSetAttribute(gemmAB_mma, cudaFuncAttributeMaxDynamicSharedMemorySize, SMEM3);

    // 1. row dots + input transposes
    rowdotC_kernel<<<(Bb*Nn)/8, 256>>>(C, w);
    rowdotQ_kernel<<<(Bb*Mm)/8, 256>>>(Q, w);
    transposeC_kernel<<<dim3(Dd/32, Nn/32, Bb), 256>>>(C);
    transposeQ_kernel<<<dim3(Dd/32, Mm/32, Bb), 256>>>(Q);

    // 2. E = exp(S)   (tensor core, bf16x3, double-buffered staging)
    gemmS_mma<<<dim3(Mm/BN, Nn/BM, Bb), 256, SMEM2>>>(C, Q, w);

    // 3. E^T + masked reductions
    transposeE_kernel<<<dim3(Mm/32, Nn/32, Bb), 256>>>();
    rowsum_kernel<<<(Bb*Nn)/8, 256>>>(Qmask);
    colsumT_kernel<<<(Bb*Mm)/8, 256>>>(Cmask);

    // 4. T^T (tensor core)
    gemmT_mma<<<dim3(Mm/BN, Dd/BM, Bb), 256, SMEM2>>>(Cmask);

    // 5. A and Bout (tensor core, fused)
    gemmAB_mma<<<dim3(Dd/BN, Nn/BM, Bb), 256, SMEM3>>>(Qmask, outA, outB);
}

// round 12
// speedup vs baseline: 1.0092x; 1.0092x over previous
#include <cuda_runtime.h>
#include <cuda_bf16.h>
#include <cstdint>
#include <math.h>

#define Bb 32
#define Nn 2048
#define Mm 512
#define Dd 512

#define BM 128
#define BN 64
#define BK 32
#define PK 40   // smem pitch in bf16 elements

// ---------------------------------------------------------------------------
// Scratch — 448MB total, overlaid lifetimes:
//   g_Big*: phase 2 = (C*w3)[n][d]; phase >=3.5 = C^T [d][n]
//   g_Sm* : phase 2 = Q [m][d]    ; phase >=4   = rcpCol*!Qmask*T^T [d][m]
// NOTE: device globals are ONLY referenced from device code (host-side symbol
// args were the root cause of the round-4/6/7/9/11 failures).
// ---------------------------------------------------------------------------
__device__ __align__(16) uint16_t g_BigH[(size_t)Bb*Nn*Dd], g_BigL[(size_t)Bb*Nn*Dd];
__device__ __align__(16) uint16_t g_SmH [(size_t)Bb*Mm*Dd], g_SmL [(size_t)Bb*Mm*Dd];
__device__ __align__(16) uint16_t g_Qth [(size_t)Bb*Mm*Dd], g_Qtl [(size_t)Bb*Mm*Dd];
__device__ __align__(16) uint16_t g_Eh  [(size_t)Bb*Nn*Mm], g_El  [(size_t)Bb*Nn*Mm];
__device__ __align__(16) uint16_t g_Eth [(size_t)Bb*Nn*Mm], g_Etl [(size_t)Bb*Nn*Mm];
__device__ __align__(16) float g_rowC[Bb*Nn], g_rowQ[Bb*Mm];
__device__ __align__(16) float g_rcpRow[Bb*Nn], g_rcpCol[Bb*Mm];

// ---------------------------------------------------------------------------
// Helpers
// ---------------------------------------------------------------------------
__device__ __forceinline__ uint32_t smem_u32(const void* p){
    uint32_t a;
    asm("{ .reg .u64 t; cvta.to.shared.u64 t, %1; cvt.u32.u64 %0, t; }"
        : "=r"(a) : "l"(p));
    return a;
}
__device__ __forceinline__ void ldm_x4(uint32_t* r, const uint16_t* p){
    uint32_t a = smem_u32(p);
    asm volatile("ldmatrix.sync.aligned.m8n8.x4.shared.b16 {%0,%1,%2,%3}, [%4];"
        : "=r"(r[0]), "=r"(r[1]), "=r"(r[2]), "=r"(r[3]) : "r"(a));
}
__device__ __forceinline__ void mma_bf16(float* c, const uint32_t* a,
                                         uint32_t b0, uint32_t b1){
    asm volatile("mma.sync.aligned.m16n8k16.row.col.f32.bf16.bf16.f32 "
        "{%0,%1,%2,%3}, {%4,%5,%6,%7}, {%8,%9}, {%0,%1,%2,%3};"
        : "+f"(c[0]), "+f"(c[1]), "+f"(c[2]), "+f"(c[3])
        : "r"(a[0]), "r"(a[1]), "r"(a[2]), "r"(a[3]), "r"(b0), "r"(b1));
}
__device__ __forceinline__ uint32_t pack2(float a, float b){
    __nv_bfloat162 t = __floats2bfloat162_rn(a, b);
    return *reinterpret_cast<uint32_t*>(&t);
}
__device__ __forceinline__ void split1(float v, float& h, float& l){
    h = __bfloat162float(__float2bfloat16_rn(v));
    l = v - h;
}

// ---------------------------------------------------------------------------
// Pre-split bf16 fragments (pure-copy staging, register double buffering)
// ---------------------------------------------------------------------------
template<int ROWS> struct BFrag { uint4 h[ROWS/64], l[ROWS/64]; };

template<int ROWS>
__device__ __forceinline__ void bf_load(BFrag<ROWS>& f,
    const uint16_t* __restrict__ gh, const uint16_t* __restrict__ gl,
    int pitch, int k0, int tid)
{
#pragma unroll
    for (int it = 0; it < ROWS/64; it++){
        int c = tid + 256*it;
        int row = c >> 2, q = (c & 3)*8;
        f.h[it] = *reinterpret_cast<const uint4*>(gh + (size_t)row*pitch + k0 + q);
        f.l[it] = *reinterpret_cast<const uint4*>(gl + (size_t)row*pitch + k0 + q);
    }
}
template<int ROWS>
__device__ __forceinline__ void bf_stage(const BFrag<ROWS>& f,
    uint16_t* __restrict__ hi, uint16_t* __restrict__ lo, int tid)
{
#pragma unroll
    for (int it = 0; it < ROWS/64; it++){
        int c = tid + 256*it;
        int row = c >> 2, q = (c & 3)*8;
        *reinterpret_cast<uint4*>(hi + row*PK + q) = f.h[it];
        *reinterpret_cast<uint4*>(lo + row*PK + q) = f.l[it];
    }
}

// ---------------------------------------------------------------------------
// Warp MMA on one staged BK=32 chunk; warp tile 32x32; bf16x3 (hh+hl+lh)
// ---------------------------------------------------------------------------
__device__ __forceinline__ void warp_mma_tile(
    float acc[2][4][4],
    const uint16_t* __restrict__ Ahi, const uint16_t* __restrict__ Alo,
    const uint16_t* __restrict__ Bhi, const uint16_t* __restrict__ Blo,
    int wm, int wn, int lane)
{
    int rsel = lane & 15;
    int ksel = (lane >> 4) * 8;
#pragma unroll
    for (int ks = 0; ks < 2; ks++){
        uint32_t ah[2][4], al[2][4];
#pragma unroll
        for (int mt = 0; mt < 2; mt++){
            ldm_x4(ah[mt], Ahi + (wm*32 + mt*16 + rsel)*PK + ks*16 + ksel);
            ldm_x4(al[mt], Alo + (wm*32 + mt*16 + rsel)*PK + ks*16 + ksel);
        }
        uint32_t bh[2][4], bl[2][4];
#pragma unroll
        for (int g = 0; g < 2; g++){
            ldm_x4(bh[g], Bhi + (wn*32 + g*16 + rsel)*PK + ks*16 + ksel);
            ldm_x4(bl[g], Blo + (wn*32 + g*16 + rsel)*PK + ks*16 + ksel);
        }
#pragma unroll
        for (int mt = 0; mt < 2; mt++)
#pragma unroll
        for (int nt = 0; nt < 4; nt++){
            uint32_t b0h = bh[nt>>1][nt & 1], b1h = bh[nt>>1][(nt & 1) + 2];
            uint32_t b0l = bl[nt>>1][nt & 1], b1l = bl[nt>>1][(nt & 1) + 2];
            mma_bf16(acc[mt][nt], ah[mt], b0h, b1h);
            mma_bf16(acc[mt][nt], ah[mt], b0l, b1l);
            mma_bf16(acc[mt][nt], al[mt], b0h, b1h);
        }
    }
}

// ---------------------------------------------------------------------------
// Prep bodies (device) + per-destination wrappers (globals bound in device code)
// ---------------------------------------------------------------------------
__device__ __forceinline__ void cvt_direct_body(
    const float* __restrict__ src, uint16_t* dh, uint16_t* dl,
    const float* __restrict__ wvec)
{
    size_t i = ((size_t)blockIdx.x*256 + threadIdx.x)*4;
    float4 v = *reinterpret_cast<const float4*>(src + i);
    if (wvec){
        int d = (int)(i & (Dd - 1));
        float4 wv = *reinterpret_cast<const float4*>(wvec + d);
        v.x *= wv.x; v.y *= wv.y; v.z *= wv.z; v.w *= wv.w;
    }
    float hx,lx,hy,ly,hz,lz,hw,lw;
    split1(v.x,hx,lx); split1(v.y,hy,ly); split1(v.z,hz,lz); split1(v.w,hw,lw);
    uint2 uh = { pack2(hx,hy), pack2(hz,hw) };
    uint2 ul = { pack2(lx,ly), pack2(lz,lw) };
    *reinterpret_cast<uint2*>(dh + i) = uh;
    *reinterpret_cast<uint2*>(dl + i) = ul;
}
__global__ void cvt_CW(const float* __restrict__ C, const float* __restrict__ w)
{ cvt_direct_body(C, g_BigH, g_BigL, w + 2*Dd); }
__global__ void cvt_Q(const float* __restrict__ Q)
{ cvt_direct_body(Q, g_SmH, g_SmL, nullptr); }

__device__ __forceinline__ void cvt_trans_body(
    const float* __restrict__ src, uint16_t* dh, uint16_t* dl,
    const int* __restrict__ mask, int R, int Cl)
{
    __shared__ float t[32][33];
    int b = blockIdx.z;
    const float* s = src + (size_t)b*R*Cl;
    int c0 = blockIdx.x*32, r0 = blockIdx.y*32;
    int tx = threadIdx.x & 31, ty = threadIdx.x >> 5;
    const int* mk = mask ? mask + b*R : nullptr;
#pragma unroll
    for (int j = 0; j < 4; j++){
        int r = ty + 8*j;
        float v = s[(size_t)(r0 + r)*Cl + c0 + tx];
        if (mk && mk[r0 + r]) v = 0.f;
        t[r][tx] = v;
    }
    __syncthreads();
    size_t ob = (size_t)b*R*Cl;
#pragma unroll
    for (int p = 0; p < 2; p++){
        int oc = (threadIdx.x >> 4) + p*16;
        int pr = (threadIdx.x & 15)*2;
        float v0 = t[pr][oc], v1 = t[pr+1][oc];
        float h0,l0,h1,l1;
        split1(v0,h0,l0); split1(v1,h1,l1);
        size_t o = ob + (size_t)(c0 + oc)*R + r0 + pr;
        *reinterpret_cast<uint32_t*>(dh + o) = pack2(h0,h1);
        *reinterpret_cast<uint32_t*>(dl + o) = pack2(l0,l1);
    }
}
__global__ void __launch_bounds__(256) cvt_Ct(const float* __restrict__ C)
{ cvt_trans_body(C, g_BigH, g_BigL, nullptr, Nn, Dd); }
__global__ void __launch_bounds__(256) cvt_Qt(const float* __restrict__ Q,
                                              const int* __restrict__ Qmask)
{ cvt_trans_body(Q, g_Qth, g_Qtl, Qmask, Mm, Dd); }

// E (bf16 hi/lo, [n][m]) -> Cmask-folded E^T (bf16 hi/lo, [m][n])
__global__ void __launch_bounds__(256) trans_bf(const int* __restrict__ Cmask)
{
    __shared__ uint16_t th[64][33], tl[64][33];
    int b = blockIdx.z;
    int n0 = blockIdx.y*32, m0 = blockIdx.x*64;
    const uint32_t* sh = (const uint32_t*)(g_Eh + (size_t)b*Nn*Mm);
    const uint32_t* sl = (const uint32_t*)(g_El + (size_t)b*Nn*Mm);
    const int* cm = Cmask + b*Nn;
    int lane = threadIdx.x & 31, w = threadIdx.x >> 5;
#pragma unroll
    for (int j = 0; j < 4; j++){
        int r = w + 8*j;
        uint32_t uh = sh[(size_t)(n0 + r)*(Mm/2) + m0/2 + lane];
        uint32_t ul = sl[(size_t)(n0 + r)*(Mm/2) + m0/2 + lane];
        if (cm[n0 + r]){ uh = 0; ul = 0; }
        th[2*lane  ][r] = (uint16_t)(uh & 0xFFFF);  th[2*lane+1][r] = (uint16_t)(uh >> 16);
        tl[2*lane  ][r] = (uint16_t)(ul & 0xFFFF);  tl[2*lane+1][r] = (uint16_t)(ul >> 16);
    }
    __syncthreads();
    uint32_t* dh = (uint32_t*)(g_Eth + (size_t)b*Nn*Mm);
    uint32_t* dl = (uint32_t*)(g_Etl + (size_t)b*Nn*Mm);
    int om = threadIdx.x >> 2, q = threadIdx.x & 3;
#pragma unroll
    for (int j = 0; j < 4; j++){
        int n = (q*4 + j)*2;
        uint32_t uh = (uint32_t)th[om][n] | ((uint32_t)th[om][n+1] << 16);
        uint32_t ul = (uint32_t)tl[om][n] | ((uint32_t)tl[om][n+1] << 16);
        size_t o = ((size_t)(m0 + om)*Nn + n0 + n) >> 1;
        dh[o] = uh; dl[o] = ul;
    }
}

// ---------------------------------------------------------------------------
// Row dots (fp32 inputs)
// ---------------------------------------------------------------------------
__global__ void rowdotC_kernel(const float* __restrict__ C, const float* __restrict__ w)
{
    int warp = (blockIdx.x*blockDim.x + threadIdx.x) >> 5;
    int lane = threadIdx.x & 31;
    if (warp >= Bb*Nn) return;
    const float4* x4 = reinterpret_cast<const float4*>(C + (size_t)warp*Dd);
    const float4* w4 = reinterpret_cast<const float4*>(w);
    float s = 0.f;
#pragma unroll
    for (int j = 0; j < 4; j++){
        float4 a = x4[lane + j*32]; float4 b = w4[lane + j*32];
        s += a.x*b.x + a.y*b.y + a.z*b.z + a.w*b.w;
    }
#pragma unroll
    for (int o = 16; o; o >>= 1) s += __shfl_xor_sync(~0u, s, o);
    if (lane == 0) g_rowC[warp] = s;
}
__global__ void rowdotQ_kernel(const float* __restrict__ Q, const float* __restrict__ w)
{
    int warp = (blockIdx.x*blockDim.x + threadIdx.x) >> 5;
    int lane = threadIdx.x & 31;
    if (warp >= Bb*Mm) return;
    const float4* x4 = reinterpret_cast<const float4*>(Q + (size_t)warp*Dd);
    const float4* w4 = reinterpret_cast<const float4*>(w + Dd);
    float s = 0.f;
#pragma unroll
    for (int j = 0; j < 4; j++){
        float4 a = x4[lane + j*32]; float4 b = w4[lane + j*32];
        s += a.x*b.x + a.y*b.y + a.z*b.z + a.w*b.w;
    }
#pragma unroll
    for (int o = 16; o; o >>= 1) s += __shfl_xor_sync(~0u, s, o);
    if (lane == 0) g_rowQ[warp] = s;
}

// ---------------------------------------------------------------------------
// Masked reductions over split E -> reciprocals
// ---------------------------------------------------------------------------
__global__ void rowsumE(const int* __restrict__ Qmask)
{
    int warp = (blockIdx.x*blockDim.x + threadIdx.x) >> 5;
    int lane = threadIdx.x & 31;
    if (warp >= Bb*Nn) return;
    int b = warp / Nn;
    const uint32_t* eh = (const uint32_t*)(g_Eh + (size_t)warp*Mm);
    const uint32_t* el = (const uint32_t*)(g_El + (size_t)warp*Mm);
    const int2* qm = (const int2*)(Qmask + b*Mm);
    float s = 0.f;
#pragma unroll
    for (int j = 0; j < 8; j++){
        uint32_t uh = eh[lane + 32*j], ul = el[lane + 32*j];
        int2 q = qm[lane + 32*j];
        __nv_bfloat162 bh = *(__nv_bfloat162*)&uh, bl = *(__nv_bfloat162*)&ul;
        float v0 = __bfloat162float(bh.x) + __bfloat162float(bl.x);
        float v1 = __bfloat162float(bh.y) + __bfloat162float(bl.y);
        s += (q.x ? 0.f : v0) + (q.y ? 0.f : v1);
    }
#pragma unroll
    for (int o = 16; o; o >>= 1) s += __shfl_xor_sync(~0u, s, o);
    if (lane == 0) g_rcpRow[warp] = 1.f / s;
}
__global__ void colsumEt()
{
    int warp = (blockIdx.x*blockDim.x + threadIdx.x) >> 5;
    int lane = threadIdx.x & 31;
    if (warp >= Bb*Mm) return;
    const uint32_t* eh = (const uint32_t*)(g_Eth + (size_t)warp*Nn);
    const uint32_t* el = (const uint32_t*)(g_Etl + (size_t)warp*Nn);
    float s = 0.f;
#pragma unroll
    for (int j = 0; j < 32; j++){
        uint32_t uh = eh[lane + 32*j], ul = el[lane + 32*j];
        __nv_bfloat162 bh = *(__nv_bfloat162*)&uh, bl = *(__nv_bfloat162*)&ul;
        s += __bfloat162float(bh.x) + __bfloat162float(bl.x)
           + __bfloat162float(bh.y) + __bfloat162float(bl.y);
    }
#pragma unroll
    for (int o = 16; o; o >>= 1) s += __shfl_xor_sync(~0u, s, o);
    if (lane == 0) g_rcpCol[warp] = 1.f / s;
}

// ---------------------------------------------------------------------------
// gemmS: E = exp(rowC + rowQ + CW·Q^T) — A=g_Big(CW), B=g_Sm(Q); writes E h/l
// ---------------------------------------------------------------------------
__global__ void __launch_bounds__(256) gemmS_mma()
{
    __shared__ __align__(16) uint16_t Ah[BM*PK], Al[BM*PK], Bh[BN*PK], Bl[BN*PK];
    int tid = threadIdx.x, lane = tid & 31, wid = tid >> 5;
    int wm = wid >> 1, wn = wid & 1;
    int b = blockIdx.z, n0 = blockIdx.y*BM, m0 = blockIdx.x*BN;
    const uint16_t* gAh = g_BigH + ((size_t)b*Nn + n0)*Dd;
    const uint16_t* gAl = g_BigL + ((size_t)b*Nn + n0)*Dd;
    const uint16_t* gBh = g_SmH  + ((size_t)b*Mm + m0)*Dd;
    const uint16_t* gBl = g_SmL  + ((size_t)b*Mm + m0)*Dd;

    BFrag<BM> fa; BFrag<BN> fb;
    bf_load(fa, gAh, gAl, Dd, 0, tid);
    bf_load(fb, gBh, gBl, Dd, 0, tid);

    float acc[2][4][4] = {};
    for (int k0 = 0; k0 < Dd; k0 += BK){
        __syncthreads();
        bf_stage(fa, Ah, Al, tid);
        bf_stage(fb, Bh, Bl, tid);
        __syncthreads();
        if (k0 + BK < Dd){
            bf_load(fa, gAh, gAl, Dd, k0 + BK, tid);
            bf_load(fb, gBh, gBl, Dd, k0 + BK, tid);
        }
        warp_mma_tile(acc, Ah, Al, Bh, Bl, wm, wn, lane);
    }

    int rg = lane >> 2, cg = (lane & 3)*2;
#pragma unroll
    for (int mt = 0; mt < 2; mt++)
#pragma unroll
    for (int nt = 0; nt < 4; nt++)
#pragma unroll
    for (int h = 0; h < 2; h++){
        int n = n0 + wm*32 + mt*16 + rg + h*8;
        int m = m0 + wn*32 + nt*8 + cg;
        float rc = g_rowC[b*Nn + n];
        float e0 = __expf(acc[mt][nt][h*2+0] + rc + g_rowQ[b*Mm + m + 0]);
        float e1 = __expf(acc[mt][nt][h*2+1] + rc + g_rowQ[b*Mm + m + 1]);
        float h0,l0,h1,l1;
        split1(e0,h0,l0); split1(e1,h1,l1);
        size_t o = ((size_t)b*Nn + n)*Mm + m;
        *reinterpret_cast<uint32_t*>(g_Eh + o) = pack2(h0,h1);
        *reinterpret_cast<uint32_t*>(g_El + o) = pack2(l0,l1);
    }
}

// ---------------------------------------------------------------------------
// gemmT: Tt[d][m] = rcpCol[m]*!Qmask[m] * sum_n Ct[d,n]*Etm[m,n]
// A=g_Big(now Ct), B=g_Et; writes Tt h/l into g_Sm (Q's buffer, now dead)
// ---------------------------------------------------------------------------
__global__ void __launch_bounds__(256) gemmT_mma(const int* __restrict__ Qmask)
{
    __shared__ __align__(16) uint16_t Ah[BM*PK], Al[BM*PK], Bh[BN*PK], Bl[BN*PK];
    int tid = threadIdx.x, lane = tid & 31, wid = tid >> 5;
    int wm = wid >> 1, wn = wid & 1;
    int b = blockIdx.z, d0 = blockIdx.y*BM, m0 = blockIdx.x*BN;
    const uint16_t* gAh = g_BigH + ((size_t)b*Dd + d0)*Nn;
    const uint16_t* gAl = g_BigL + ((size_t)b*Dd + d0)*Nn;
    const uint16_t* gBh = g_Eth  + ((size_t)b*Mm + m0)*Nn;
    const uint16_t* gBl = g_Etl  + ((size_t)b*Mm + m0)*Nn;

    BFrag<BM> fa; BFrag<BN> fb;
    bf_load(fa, gAh, gAl, Nn, 0, tid);
    bf_load(fb, gBh, gBl, Nn, 0, tid);

    float acc[2][4][4] = {};
    for (int k0 = 0; k0 < Nn; k0 += BK){
        __syncthreads();
        bf_stage(fa, Ah, Al, tid);
        bf_stage(fb, Bh, Bl, tid);
        __syncthreads();
        if (k0 + BK < Nn){
            bf_load(fa, gAh, gAl, Nn, k0 + BK, tid);
            bf_load(fb, gBh, gBl, Nn, k0 + BK, tid);
        }
        warp_mma_tile(acc, Ah, Al, Bh, Bl, wm, wn, lane);
    }

    int rg = lane >> 2, cg = (lane & 3)*2;
#pragma unroll
    for (int mt = 0; mt < 2; mt++)
#pragma unroll
    for (int nt = 0; nt < 4; nt++)
#pragma unroll
    for (int h = 0; h < 2; h++){
        int d = d0 + wm*32 + mt*16 + rg + h*8;
        int m = m0 + wn*32 + nt*8 + cg;
        float v0 = acc[mt][nt][h*2+0] * g_rcpCol[b*Mm + m + 0];
        float v1 = acc[mt][nt][h*2+1] * g_rcpCol[b*Mm + m + 1];
        if (Qmask[b*Mm + m + 0]) v0 = 0.f;
        if (Qmask[b*Mm + m + 1]) v1 = 0.f;
        float h0,l0,h1,l1;
        split1(v0,h0,l0); split1(v1,h1,l1);
        size_t o = ((size_t)b*Dd + d)*Mm + m;
        *reinterpret_cast<uint32_t*>(g_SmH + o) = pack2(h0,h1);
        *reinterpret_cast<uint32_t*>(g_SmL + o) = pack2(l0,l1);
    }
}

// ---------------------------------------------------------------------------
// gemmAB: A = rcpRow * E·Qtm^T ; Bout = rcpRow * E·Ttm^T   (Tt in g_Sm)
// ---------------------------------------------------------------------------
__global__ void __launch_bounds__(256) gemmAB_mma(
    float* __restrict__ outA, float* __restrict__ outB)
{
    __shared__ __align__(16) uint16_t Ah[BM*PK], Al[BM*PK];
    __shared__ __align__(16) uint16_t B1h[BN*PK], B1l[BN*PK], B2h[BN*PK], B2l[BN*PK];
    int tid = threadIdx.x, lane = tid & 31, wid = tid >> 5;
    int wm = wid >> 1, wn = wid & 1;
    int b = blockIdx.z, n0 = blockIdx.y*BM, d0 = blockIdx.x*BN;
    const uint16_t* gAh  = g_Eh  + ((size_t)b*Nn + n0)*Mm;
    const uint16_t* gAl  = g_El  + ((size_t)b*Nn + n0)*Mm;
    const uint16_t* gB1h = g_Qth + ((size_t)b*Dd + d0)*Mm;
    const uint16_t* gB1l = g_Qtl + ((size_t)b*Dd + d0)*Mm;
    const uint16_t* gB2h = g_SmH + ((size_t)b*Dd + d0)*Mm;
    const uint16_t* gB2l = g_SmL + ((size_t)b*Dd + d0)*Mm;

    BFrag<BM> fa; BFrag<BN> fb1, fb2;
    bf_load(fa,  gAh,  gAl,  Mm, 0, tid);
    bf_load(fb1, gB1h, gB1l, Mm, 0, tid);
    bf_load(fb2, gB2h, gB2l, Mm, 0, tid);

    float accA[2][4][4] = {};
    float accB[2][4][4] = {};
    for (int k0 = 0; k0 < Mm; k0 += BK){
        __syncthreads();
        bf_stage(fa,  Ah,  Al,  tid);
        bf_stage(fb1, B1h, B1l, tid);
        bf_stage(fb2, B2h, B2l, tid);
        __syncthreads();
        if (k0 + BK < Mm){
            bf_load(fa,  gAh,  gAl,  Mm, k0 + BK, tid);
            bf_load(fb1, gB1h, gB1l, Mm, k0 + BK, tid);
            bf_load(fb2, gB2h, gB2l, Mm, k0 + BK, tid);
        }
        warp_mma_tile(accA, Ah, Al, B1h, B1l, wm, wn, lane);
        warp_mma_tile(accB, Ah, Al, B2h, B2l, wm, wn, lane);
    }

    int rg = lane >> 2, cg = (lane & 3)*2;
#pragma unroll
    for (int mt = 0; mt < 2; mt++)
#pragma unroll
    for (int nt = 0; nt < 4; nt++)
#pragma unroll
    for (int h = 0; h < 2; h++){
        int n = n0 + wm*32 + mt*16 + rg + h*8;
        int d = d0 + wn*32 + nt*8 + cg;
        float rr = g_rcpRow[b*Nn + n];
        size_t idx = ((size_t)b*Nn + n)*Dd + d;
        float2 oa = { accA[mt][nt][h*2+0]*rr, accA[mt][nt][h*2+1]*rr };
        float2 ob = { accB[mt][nt][h*2+0]*rr, accB[mt][nt][h*2+1]*rr };
        *reinterpret_cast<float2*>(&outA[idx]) = oa;
        *reinterpret_cast<float2*>(&outB[idx]) = ob;
    }
}

// ---------------------------------------------------------------------------
extern "C" void kernel_launch(void* const* d_in, const int* in_sizes, int n_in,
                              void* d_out, int out_size)
{
    const float* C     = (const float*)d_in[0];
    const float* Q     = (const float*)d_in[1];
    const int*   Cmask = (const int*)d_in[2];
    const int*   Qmask = (const int*)d_in[3];
    const float* w     = (const float*)d_in[4];

    float* outA = (float*)d_out;
    float* outB = outA + (size_t)Bb*Nn*Dd;

    // 1. row dots + pre-splits: CW -> g_Big, Q -> g_Sm, masked Q^T -> g_Qt
    rowdotC_kernel<<<(Bb*Nn)/8, 256>>>(C, w);
    rowdotQ_kernel<<<(Bb*Mm)/8, 256>>>(Q, w);
    cvt_CW<<<(int)(((size_t)Bb*Nn*Dd)/1024), 256>>>(C, w);
    cvt_Q <<<(int)(((size_t)Bb*Mm*Dd)/1024), 256>>>(Q);
    cvt_Qt<<<dim3(Dd/32, Mm/32, Bb), 256>>>(Q, Qmask);

    // 2. E = exp(S)  (consumes g_Big=CW, g_Sm=Q)
    gemmS_mma<<<dim3(Mm/BN, Nn/BM, Bb), 256>>>();

    // 3. C^T -> g_Big (overwrites CW, now dead); E^T + reductions
    cvt_Ct<<<dim3(Dd/32, Nn/32, Bb), 256>>>(C);
    trans_bf<<<dim3(Mm/64, Nn/32, Bb), 256>>>(Cmask);
    rowsumE<<<(Bb*Nn)/8, 256>>>(Qmask);
    colsumEt<<<(Bb*Mm)/8, 256>>>();

    // 4. T^T -> g_Sm (overwrites Q, now dead)
    gemmT_mma<<<dim3(Mm/BN, Dd/BM, Bb), 256>>>(Qmask);

    // 5. A and Bout
    gemmAB_mma<<<dim3(Dd/BN, Nn/BM, Bb), 256>>>(outA, outB);
}